// round 15
// baseline (speedup 1.0000x reference)
#include <cuda_runtime.h>
#include <cuda_bf16.h>
#include <math.h>
#include <stdint.h>

#define Tn  128
#define Dn  1024
#define Ln  8
#define Hn  16
#define Fn  2816
#define DHn 64
#define Vn  32000
#define TnDn (Tn*Dn)
#define TnFn (Tn*Fn)

// transposed bf16 hi/lo weight cache offsets (elements)
#define WQ_OFF 0ull
#define WK_OFF 8388608ull
#define WV_OFF 16777216ull
#define WO_OFF 25165824ull
#define WG_OFF 33554432ull
#define WU_OFF 56623104ull
#define WD_OFF 79691776ull
#define W_TOTAL 102760448ull

// ---- scratch ----
__device__ float g_X [TnDn];
__device__ float g_Q [TnDn];
__device__ float g_Kc[TnDn];
__device__ float g_Vc[TnDn];
__device__ float g_part[12 * TnDn];
__device__ float g_xl[Dn];
__device__ float g_tmp[12288];
__device__ float g_ropec[Tn * 32], g_ropes[Tn * 32];
__device__ __nv_bfloat16 g_XNh[TnDn], g_XNl[TnDn];
__device__ __nv_bfloat16 g_Ah [TnDn], g_Al [TnDn];
__device__ __nv_bfloat16 g_Hh [TnFn], g_Hl [TnFn];
__device__ __nv_bfloat16 g_hrh[Fn], g_hrl[Fn];
__device__ __nv_bfloat16 g_Wh[W_TOTAL], g_Wl[W_TOTAL];   // 411 MB weight cache

// ---- helpers ----
__device__ __forceinline__ uint32_t smem_u32(const void* p) {
    uint32_t a;
    asm("{ .reg .u64 t; cvta.to.shared.u64 t, %1; cvt.u32.u64 %0, t; }" : "=r"(a) : "l"(p));
    return a;
}
#define LDSM_X4(r0, r1, r2, r3, a) \
    asm volatile("ldmatrix.sync.aligned.m8n8.x4.shared.b16 {%0,%1,%2,%3}, [%4];" \
                 : "=r"(r0), "=r"(r1), "=r"(r2), "=r"(r3) : "r"(a))

__device__ __forceinline__ void mma_bf16(float* d, const uint32_t* a, const uint32_t* b) {
    asm volatile("mma.sync.aligned.m16n8k16.row.col.f32.bf16.bf16.f32 "
                 "{%0,%1,%2,%3}, {%4,%5,%6,%7}, {%8,%9}, {%0,%1,%2,%3};"
                 : "+f"(d[0]), "+f"(d[1]), "+f"(d[2]), "+f"(d[3])
                 : "r"(a[0]), "r"(a[1]), "r"(a[2]), "r"(a[3]), "r"(b[0]), "r"(b[1]));
}
__device__ __forceinline__ void cp16(uint32_t dst, const void* src) {
    asm volatile("cp.async.cg.shared.global [%0], [%1], 16;" :: "r"(dst), "l"(src));
}
#define CP_COMMIT() asm volatile("cp.async.commit_group;")
#define CP_WAIT0()  asm volatile("cp.async.wait_group 0;")

// ---- weight convert: src [K,N] fp32 (L layers) -> g_Wh/g_Wl [N][K] bf16 hi/lo
__global__ void __launch_bounds__(256)
k_wconv(const float* __restrict__ src, unsigned long long baseoff, int K, int N) {
    __shared__ float t[32][33];
    const float* s = src + (size_t)blockIdx.z * K * N;
    size_t doff = baseoff + (size_t)blockIdx.z * K * N;
    int k0 = blockIdx.y * 32, n0 = blockIdx.x * 32;
    int tid = threadIdx.x;
#pragma unroll
    for (int j = 0; j < 4; j++) {
        int idx = tid + j * 256;
        int r = idx >> 5, c = idx & 31;           // r: k-local, c: n-local
        t[r][c] = s[(size_t)(k0 + r) * N + n0 + c];
    }
    __syncthreads();
#pragma unroll
    for (int j = 0; j < 4; j++) {
        int idx = tid + j * 256;
        int r = idx >> 5, c = idx & 31;           // r: n-local, c: k-local
        float x = t[c][r];
        __nv_bfloat16 hh = __float2bfloat16(x);
        size_t o = doff + (size_t)(n0 + r) * K + k0 + c;
        g_Wh[o] = hh;
        g_Wl[o] = __float2bfloat16(x - __bfloat162float(hh));
    }
}

// ---- GEMM core: C[128x64] = Ahl[128,K] * Whl^T tile. 256 thr, 8 warps,
// both operands bf16 via cp.async, double-buffered. Same numerics as r14.
#define PITCHB 144
#define SM_AH(s) ((s) * 18432)
#define SM_AL(s) (36864 + (s) * 18432)
#define SM_BH(s) (73728 + (s) * 9216)
#define SM_BL(s) (92160 + (s) * 9216)
#define SMEM_BYTES 110592

__device__ void gemm_core(const __nv_bfloat16* __restrict__ Ah,
                          const __nv_bfloat16* __restrict__ Al, int lda,
                          const __nv_bfloat16* __restrict__ Bh,
                          const __nv_bfloat16* __restrict__ Bl, int ldb,
                          float* __restrict__ Cp, int ldc,
                          int k0, int nkb, int n0)
{
    extern __shared__ unsigned char sm[];
    const uint32_t smb = smem_u32(sm);
    const int tid = threadIdx.x, w = tid >> 5, lane = tid & 31;
    const int gID = lane >> 2, tig = lane & 3;

    float c[8][4] = {};

    const int a_r = lane & 15, a_h = lane >> 4;
    const int b_nr = ((lane >> 4) << 3) | (lane & 7);
    const int b_kh = (lane >> 3) & 1;

    // stage helper indices: A chunks idx>>3 = row, (idx&7)*8 = k8 (4/thread)
    //                       B chunks idx>>3 = n-row, (idx&7)*8 = k8 (2/thread)
    {
#pragma unroll
        for (int j = 0; j < 4; j++) {
            int idx = tid + j * 256;
            int m = idx >> 3, k8 = (idx & 7) << 3;
            uint32_t off = (uint32_t)m * PITCHB + k8 * 2;
            cp16(smb + SM_AH(0) + off, Ah + (size_t)m * lda + k0 + k8);
            cp16(smb + SM_AL(0) + off, Al + (size_t)m * lda + k0 + k8);
        }
#pragma unroll
        for (int j = 0; j < 2; j++) {
            int idx = tid + j * 256;
            int r = idx >> 3, k8 = (idx & 7) << 3;
            uint32_t off = (uint32_t)r * PITCHB + k8 * 2;
            cp16(smb + SM_BH(0) + off, Bh + (size_t)(n0 + r) * ldb + k0 + k8);
            cp16(smb + SM_BL(0) + off, Bl + (size_t)(n0 + r) * ldb + k0 + k8);
        }
        CP_COMMIT();
    }

    for (int it = 0; it < nkb; ++it) {
        const int buf = it & 1;
        const int kc = k0 + it * 64;
        CP_WAIT0();
        __syncthreads();

        if (it + 1 < nkb) {
            const int kn = kc + 64;
            const int nb = buf ^ 1;
#pragma unroll
            for (int j = 0; j < 4; j++) {
                int idx = tid + j * 256;
                int m = idx >> 3, k8 = (idx & 7) << 3;
                uint32_t off = (uint32_t)m * PITCHB + k8 * 2;
                cp16(smb + SM_AH(nb) + off, Ah + (size_t)m * lda + kn + k8);
                cp16(smb + SM_AL(nb) + off, Al + (size_t)m * lda + kn + k8);
            }
#pragma unroll
            for (int j = 0; j < 2; j++) {
                int idx = tid + j * 256;
                int r = idx >> 3, k8 = (idx & 7) << 3;
                uint32_t off = (uint32_t)r * PITCHB + k8 * 2;
                cp16(smb + SM_BH(nb) + off, Bh + (size_t)(n0 + r) * ldb + kn + k8);
                cp16(smb + SM_BL(nb) + off, Bl + (size_t)(n0 + r) * ldb + kn + k8);
            }
            CP_COMMIT();
        }

        const uint32_t aH = smb + SM_AH(buf), aL = smb + SM_AL(buf);
        const uint32_t bH = smb + SM_BH(buf), bL = smb + SM_BL(buf);
#pragma unroll
        for (int s = 0; s < 4; s++) {
            uint32_t ah[4], al[4], bh[8][2], bl[8][2];
            uint32_t ao = (uint32_t)(w * 16 + a_r) * PITCHB + (s * 16 + a_h * 8) * 2;
            LDSM_X4(ah[0], ah[1], ah[2], ah[3], aH + ao);
            LDSM_X4(al[0], al[1], al[2], al[3], aL + ao);
#pragma unroll
            for (int np = 0; np < 4; np++) {
                uint32_t bo = (uint32_t)(np * 16 + b_nr) * PITCHB
                            + (s * 16 + b_kh * 8) * 2;
                LDSM_X4(bh[np*2][0], bh[np*2][1], bh[np*2+1][0], bh[np*2+1][1], bH + bo);
                LDSM_X4(bl[np*2][0], bl[np*2][1], bl[np*2+1][0], bl[np*2+1][1], bL + bo);
            }
#pragma unroll
            for (int nt = 0; nt < 8; nt++) {
                mma_bf16(c[nt], ah, bh[nt]);
                mma_bf16(c[nt], ah, bl[nt]);
                mma_bf16(c[nt], al, bh[nt]);
            }
        }
        __syncthreads();
    }

#pragma unroll
    for (int nt = 0; nt < 8; nt++) {
        int row = w * 16 + gID;
        int col = n0 + nt * 8 + tig * 2;
        *(float2*)(Cp + (size_t)row * ldc + col) = make_float2(c[nt][0], c[nt][1]);
        *(float2*)(Cp + (size_t)(row + 8) * ldc + col) = make_float2(c[nt][2], c[nt][3]);
    }
}

// ---- GEMM wrappers (weights from device cache; only layer index crosses) ----
__global__ void __launch_bounds__(256) kg_qkv(int l) {
    size_t off = ((blockIdx.z == 0) ? WQ_OFF : (blockIdx.z == 1) ? WK_OFF : WV_OFF)
               + (size_t)l * 1048576;
    float* Cp = g_part + (size_t)(blockIdx.z * 4 + blockIdx.y) * TnDn;
    gemm_core(g_XNh, g_XNl, Dn, g_Wh + off, g_Wl + off, Dn,
              Cp, Dn, blockIdx.y * 256, 4, blockIdx.x * 64);
}
__global__ void __launch_bounds__(256) kg_wo(int l) {
    size_t off = WO_OFF + (size_t)l * 1048576;
    float* Cp = g_part + (size_t)blockIdx.y * TnDn;
    gemm_core(g_Ah, g_Al, Dn, g_Wh + off, g_Wl + off, Dn,
              Cp, Dn, blockIdx.y * 128, 2, blockIdx.x * 64);
}
__global__ void __launch_bounds__(256) kg_gu(int l) {
    size_t off = ((blockIdx.z == 0) ? WG_OFF : WU_OFF) + (size_t)l * 2883584;
    float* Cp = g_part + (size_t)(blockIdx.z * 2 + blockIdx.y) * TnFn;
    gemm_core(g_XNh, g_XNl, Dn, g_Wh + off, g_Wl + off, Dn,
              Cp, Fn, blockIdx.y * 512, 8, blockIdx.x * 64);
}
__global__ void __launch_bounds__(256) kg_down(int l) {
    size_t off = WD_OFF + (size_t)l * 2883584;
    float* Cp = g_part + (size_t)blockIdx.y * TnDn;
    gemm_core(g_Hh, g_Hl, Fn, g_Wh + off, g_Wl + off, Fn,
              Cp, Dn, blockIdx.y * 256, 4, blockIdx.x * 64);
}

// ---- elementwise / reductions ----
__device__ __forceinline__ float blockReduceSum(float v) {
    __shared__ float red[32];
    __shared__ float tot;
    int lane = threadIdx.x & 31, warp = threadIdx.x >> 5;
#pragma unroll
    for (int o = 16; o > 0; o >>= 1) v += __shfl_xor_sync(0xffffffffu, v, o);
    if (lane == 0) red[warp] = v;
    __syncthreads();
    int nw = (blockDim.x + 31) >> 5;
    if (warp == 0) {
        float x = (threadIdx.x < nw) ? red[threadIdx.x] : 0.f;
#pragma unroll
        for (int o = 16; o > 0; o >>= 1) x += __shfl_xor_sync(0xffffffffu, x, o);
        if (threadIdx.x == 0) tot = x;
    }
    __syncthreads();
    return tot;
}

// RoPE table init (fp64 trig; r8/r13 proved in-kernel fp64 trig is guard-clean)
__global__ void k_rope_init() {
    int t = blockIdx.x, d = threadIdx.x;
    double inv = pow(10000.0, -(double)d / 32.0);
    double ang = (double)t * inv;
    g_ropec[t * 32 + d] = (float)cos(ang);
    g_ropes[t * 32 + d] = (float)sin(ang);
}

__global__ void k_embed(const int* __restrict__ ids, const float* __restrict__ emb) {
    int t = blockIdx.x;
    int row = ids[t];
    const float4* src = (const float4*)(emb + (size_t)row * Dn);
    float4* dst = (float4*)(g_X + (size_t)t * Dn);
    for (int i = threadIdx.x; i < Dn / 4; i += blockDim.x) dst[i] = src[i];
}

__global__ void k_addnorm(int nparts, const float* __restrict__ w) {
    int t = blockIdx.x;
    int d4 = threadIdx.x * 4;
    float4 acc = *(const float4*)(g_X + (size_t)t * Dn + d4);
    for (int p = 0; p < nparts; p++) {
        float4 pv = *(const float4*)(g_part + (size_t)p * TnDn + (size_t)t * Dn + d4);
        acc.x += pv.x; acc.y += pv.y; acc.z += pv.z; acc.w += pv.w;
    }
    *(float4*)(g_X + (size_t)t * Dn + d4) = acc;
    float ss = acc.x * acc.x + acc.y * acc.y + acc.z * acc.z + acc.w * acc.w;
    ss = blockReduceSum(ss);
    float inv = rsqrtf(ss / (float)Dn + 1e-5f);
    float4 wv = *(const float4*)(w + d4);
    float xn[4] = { acc.x * inv * wv.x, acc.y * inv * wv.y,
                    acc.z * inv * wv.z, acc.w * inv * wv.w };
#pragma unroll
    for (int i = 0; i < 4; i++) {
        __nv_bfloat16 hh = __float2bfloat16(xn[i]);
        g_XNh[(size_t)t * Dn + d4 + i] = hh;
        g_XNl[(size_t)t * Dn + d4 + i] = __float2bfloat16(xn[i] - __bfloat162float(hh));
    }
}

// QKV split-K reduce + RoPE via table. grid=Tn, block=512.
__global__ void k_qkv_rr() {
    int t = blockIdx.x;
    int hh = threadIdx.x >> 5, d = threadIdx.x & 31;
    float c = g_ropec[t * 32 + d], s = g_ropes[t * 32 + d];
    int off = t * Dn + hh * DHn + d;
#pragma unroll
    for (int m = 0; m < 3; m++) {
        size_t base = (size_t)(m * 4) * TnDn + off;
        float s0 = 0.f, s1 = 0.f;
#pragma unroll
        for (int p = 0; p < 4; p++) {
            s0 += g_part[base + (size_t)p * TnDn];
            s1 += g_part[base + (size_t)p * TnDn + 32];
        }
        float o0, o1;
        if (m < 2) { o0 = s0 * c - s1 * s; o1 = s1 * c + s0 * s; }
        else       { o0 = s0; o1 = s1; }
        float* dst = (m == 0) ? g_Q : (m == 1) ? g_Kc : g_Vc;
        dst[off] = o0;
        dst[off + 32] = o1;
    }
}

__global__ void k_silu() {
    int i = blockIdx.x * blockDim.x + threadIdx.x;
    float g = g_part[i] + g_part[(size_t)TnFn + i];
    float u = g_part[2 * (size_t)TnFn + i] + g_part[3 * (size_t)TnFn + i];
    float sv = g / (1.f + expf(-g));
    float r = sv * u;
    __nv_bfloat16 hh = __float2bfloat16(r);
    g_Hh[i] = hh;
    g_Hl[i] = __float2bfloat16(r - __bfloat162float(hh));
}

// ---- attention: 16 queries per block (r14-proven) ----
__global__ void __launch_bounds__(256) k_attn(int qg0) {
    int qg = qg0 + blockIdx.x;
    int hed = blockIdx.y;
    int tid = threadIdx.x, w = tid >> 5, lane = tid & 31;
    __shared__ float KV[Tn][DHn + 1];
    __shared__ float Qs[16][DHn];
    __shared__ float Ps[16][Tn + 1];

    for (int idx = tid; idx < Tn * DHn; idx += 256) {
        int r = idx >> 6, c = idx & 63;
        KV[r][c] = g_Kc[(size_t)r * Dn + hed * DHn + c];
    }
    for (int idx = tid; idx < 16 * DHn; idx += 256) {
        int r = idx >> 6, c = idx & 63;
        Qs[r][c] = g_Q[(size_t)(qg * 16 + r) * Dn + hed * DHn + c];
    }
    __syncthreads();

#pragma unroll
    for (int sub = 0; sub < 2; sub++) {
        int ql = w * 2 + sub;
        int q = qg * 16 + ql;
        float s[4];
#pragma unroll
        for (int jj = 0; jj < 4; jj++) {
            int j = jj * 32 + lane;
            if (j <= q) {
                float acc = 0.f;
#pragma unroll
                for (int d = 0; d < DHn; d++) acc = fmaf(Qs[ql][d], KV[j][d], acc);
                s[jj] = acc * 0.125f;
            } else s[jj] = -1e9f;
        }
        float m = fmaxf(fmaxf(s[0], s[1]), fmaxf(s[2], s[3]));
#pragma unroll
        for (int o = 16; o > 0; o >>= 1) m = fmaxf(m, __shfl_xor_sync(0xffffffffu, m, o));
        float e[4], sum = 0.f;
#pragma unroll
        for (int jj = 0; jj < 4; jj++) { e[jj] = expf(s[jj] - m); sum += e[jj]; }
#pragma unroll
        for (int o = 16; o > 0; o >>= 1) sum += __shfl_xor_sync(0xffffffffu, sum, o);
#pragma unroll
        for (int jj = 0; jj < 4; jj++) Ps[ql][jj * 32 + lane] = e[jj] / sum;
    }
    __syncthreads();

    for (int idx = tid; idx < Tn * DHn; idx += 256) {
        int r = idx >> 6, c = idx & 63;
        KV[r][c] = g_Vc[(size_t)r * Dn + hed * DHn + c];
    }
    __syncthreads();

#pragma unroll
    for (int sub = 0; sub < 2; sub++) {
        int ql = w * 2 + sub;
        int q = qg * 16 + ql;
        float o0 = 0.f, o1 = 0.f;
#pragma unroll 4
        for (int j = 0; j < Tn; j++) {
            float p = Ps[ql][j];
            o0 = fmaf(p, KV[j][lane], o0);
            o1 = fmaf(p, KV[j][lane + 32], o1);
        }
        size_t oi = (size_t)q * Dn + hed * DHn + lane;
        __nv_bfloat16 h0 = __float2bfloat16(o0);
        g_Ah[oi] = h0;
        g_Al[oi] = __float2bfloat16(o0 - __bfloat162float(h0));
        __nv_bfloat16 h1 = __float2bfloat16(o1);
        g_Ah[oi + 32] = h1;
        g_Al[oi + 32] = __float2bfloat16(o1 - __bfloat162float(h1));
    }
}

// ---- last-layer GEMV path (token 127 only; device-resolved globals) ----
__global__ void k_gemv(int src, int outoff, const float* __restrict__ W,
                       int K, int N) {
    __shared__ float red[256];
    const __nv_bfloat16 *xh, *xl;
    if (src == 0)      { xh = g_Ah  + (size_t)(Tn - 1) * Dn; xl = g_Al  + (size_t)(Tn - 1) * Dn; }
    else if (src == 1) { xh = g_XNh + (size_t)(Tn - 1) * Dn; xl = g_XNl + (size_t)(Tn - 1) * Dn; }
    else               { xh = g_hrh;                          xl = g_hrl; }
    int nsub = threadIdx.x & 15, ks = threadIdx.x >> 4;
    int n = blockIdx.x * 16 + nsub;
    float s = 0.f;
    for (int k = ks; k < K; k += 16) {
        float x = __bfloat162float(xh[k]) + __bfloat162float(xl[k]);
        s = fmaf(x, W[(size_t)k * N + n], s);
    }
    red[threadIdx.x] = s;
    __syncthreads();
    if (threadIdx.x < 16) {
        float t = 0.f;
#pragma unroll
        for (int j = 0; j < 16; j++) t += red[threadIdx.x + 16 * j];
        g_tmp[outoff + blockIdx.x * 16 + threadIdx.x] = t;
    }
}

__global__ void k_addnorm_last(const float* __restrict__ w) {
    int d4 = threadIdx.x * 4;
    size_t ro = (size_t)(Tn - 1) * Dn;
    float4 acc = *(const float4*)(g_X + ro + d4);
    float4 pv = *(const float4*)(g_tmp + d4);
    acc.x += pv.x; acc.y += pv.y; acc.z += pv.z; acc.w += pv.w;
    *(float4*)(g_X + ro + d4) = acc;
    float ss = acc.x * acc.x + acc.y * acc.y + acc.z * acc.z + acc.w * acc.w;
    ss = blockReduceSum(ss);
    float inv = rsqrtf(ss / (float)Dn + 1e-5f);
    float4 wv = *(const float4*)(w + d4);
    float xn[4] = { acc.x * inv * wv.x, acc.y * inv * wv.y,
                    acc.z * inv * wv.z, acc.w * inv * wv.w };
#pragma unroll
    for (int i = 0; i < 4; i++) {
        __nv_bfloat16 hh = __float2bfloat16(xn[i]);
        g_XNh[ro + d4 + i] = hh;
        g_XNl[ro + d4 + i] = __float2bfloat16(xn[i] - __bfloat162float(hh));
    }
}

__global__ void k_silu_last() {
    int i = blockIdx.x * blockDim.x + threadIdx.x;
    if (i < Fn) {
        float g = g_tmp[2048 + i], u = g_tmp[5120 + i];
        float sv = g / (1.f + expf(-g));
        float r = sv * u;
        __nv_bfloat16 hh = __float2bfloat16(r);
        g_hrh[i] = hh;
        g_hrl[i] = __float2bfloat16(r - __bfloat162float(hh));
    }
}

__global__ void k_finalnorm_last(const float* __restrict__ w) {
    int d4 = threadIdx.x * 4;
    size_t ro = (size_t)(Tn - 1) * Dn;
    float4 xv = *(const float4*)(g_X + ro + d4);
    float4 dv = *(const float4*)(g_tmp + 8192 + d4);
    xv.x += dv.x; xv.y += dv.y; xv.z += dv.z; xv.w += dv.w;
    float ss = xv.x * xv.x + xv.y * xv.y + xv.z * xv.z + xv.w * xv.w;
    ss = blockReduceSum(ss);
    float inv = rsqrtf(ss / (float)Dn + 1e-5f);
    float4 wv = *(const float4*)(w + d4);
    *(float4*)(g_xl + d4) = make_float4(xv.x * inv * wv.x, xv.y * inv * wv.y,
                                        xv.z * inv * wv.z, xv.w * inv * wv.w);
}

__global__ void k_logits(const float* __restrict__ emb, float* __restrict__ out) {
    __shared__ float4 xs[Dn / 4];
    for (int i = threadIdx.x; i < Dn / 4; i += blockDim.x)
        xs[i] = ((const float4*)g_xl)[i];
    __syncthreads();
    int warp = threadIdx.x >> 5, lane = threadIdx.x & 31;
    int row = blockIdx.x * 8 + warp;
    if (row < Vn) {
        const float4* e4 = (const float4*)(emb + (size_t)row * Dn);
        float s = 0.f;
#pragma unroll
        for (int k = lane; k < Dn / 4; k += 32) {
            float4 a = e4[k], b = xs[k];
            s += a.x * b.x + a.y * b.y + a.z * b.z + a.w * b.w;
        }
#pragma unroll
        for (int o = 16; o > 0; o >>= 1) s += __shfl_xor_sync(0xffffffffu, s, o);
        if (lane == 0) out[row] = s;
    }
}

// ---- host ----
extern "C" void kernel_launch(void* const* d_in, const int* in_sizes, int n_in,
                              void* d_out, int out_size) {
    const int*   ids       = (const int*)  d_in[0];
    const float* emb       = (const float*)d_in[1];
    const float* Wq        = (const float*)d_in[2];
    const float* Wk        = (const float*)d_in[3];
    const float* Wv        = (const float*)d_in[4];
    const float* Wo        = (const float*)d_in[5];
    const float* Wg        = (const float*)d_in[6];
    const float* Wu        = (const float*)d_in[7];
    const float* Wd        = (const float*)d_in[8];
    const float* attn_norm = (const float*)d_in[9];
    const float* ffn_norm  = (const float*)d_in[10];
    const float* norm_out  = (const float*)d_in[11];
    float* out = (float*)d_out;

    cudaFuncSetAttribute(kg_qkv,  cudaFuncAttributeMaxDynamicSharedMemorySize, SMEM_BYTES);
    cudaFuncSetAttribute(kg_wo,   cudaFuncAttributeMaxDynamicSharedMemorySize, SMEM_BYTES);
    cudaFuncSetAttribute(kg_gu,   cudaFuncAttributeMaxDynamicSharedMemorySize, SMEM_BYTES);
    cudaFuncSetAttribute(kg_down, cudaFuncAttributeMaxDynamicSharedMemorySize, SMEM_BYTES);

    // weight cache build (streamed once per launch)
    k_wconv<<<dim3(32, 32, Ln), 256>>>(Wq, WQ_OFF, Dn, Dn);
    k_wconv<<<dim3(32, 32, Ln), 256>>>(Wk, WK_OFF, Dn, Dn);
    k_wconv<<<dim3(32, 32, Ln), 256>>>(Wv, WV_OFF, Dn, Dn);
    k_wconv<<<dim3(32, 32, Ln), 256>>>(Wo, WO_OFF, Dn, Dn);
    k_wconv<<<dim3(88, 32, Ln), 256>>>(Wg, WG_OFF, Dn, Fn);
    k_wconv<<<dim3(88, 32, Ln), 256>>>(Wu, WU_OFF, Dn, Fn);
    k_wconv<<<dim3(32, 88, Ln), 256>>>(Wd, WD_OFF, Fn, Dn);

    k_rope_init<<<Tn, 32>>>();
    k_embed<<<Tn, 256>>>(ids, emb);

    for (int l = 0; l < Ln - 1; l++) {
        k_addnorm<<<Tn, 256>>>(l == 0 ? 0 : 11, attn_norm + (size_t)l * Dn);
        kg_qkv<<<dim3(16, 4, 3), 256, SMEM_BYTES>>>(l);
        k_qkv_rr<<<Tn, 512>>>();
        k_attn<<<dim3(8, Hn), 256>>>(0);
        kg_wo<<<dim3(16, 8), 256, SMEM_BYTES>>>(l);
        k_addnorm<<<Tn, 256>>>(8, ffn_norm + (size_t)l * Dn);
        kg_gu<<<dim3(44, 2, 2), 256, SMEM_BYTES>>>(l);
        k_silu<<<TnFn / 256, 256>>>();
        kg_down<<<dim3(16, 11), 256, SMEM_BYTES>>>(l);
    }

    // layer 7: K/V for all tokens, everything else token 127 only
    {
        const int l = Ln - 1;
        k_addnorm<<<Tn, 256>>>(11, attn_norm + (size_t)l * Dn);
        kg_qkv<<<dim3(16, 4, 3), 256, SMEM_BYTES>>>(l);
        k_qkv_rr<<<Tn, 512>>>();
        k_attn<<<dim3(1, Hn), 256>>>(7);
        k_gemv<<<Dn / 16, 256>>>(0, 0,    Wo + (size_t)l * Dn * Dn, Dn, Dn);
        k_addnorm_last<<<1, 256>>>(ffn_norm + (size_t)l * Dn);
        k_gemv<<<Fn / 16, 256>>>(1, 2048, Wg + (size_t)l * Dn * Fn, Dn, Fn);
        k_gemv<<<Fn / 16, 256>>>(1, 5120, Wu + (size_t)l * Dn * Fn, Dn, Fn);
        k_silu_last<<<(Fn + 255) / 256, 256>>>();
        k_gemv<<<Dn / 16, 256>>>(2, 8192, Wd + (size_t)l * Fn * Dn, Fn, Dn);
    }

    k_finalnorm_last<<<1, 256>>>(norm_out);
    k_logits<<<(Vn + 7) / 8, 256>>>(emb, out);
}

// round 16
// speedup vs baseline: 1.0556x; 1.0556x over previous
#include <cuda_runtime.h>
#include <cuda_bf16.h>
#include <math.h>
#include <stdint.h>

#define Tn  128
#define Dn  1024
#define Ln  8
#define Hn  16
#define Fn  2816
#define DHn 64
#define Vn  32000
#define TnDn (Tn*Dn)
#define TnFn (Tn*Fn)

// ---- scratch ----
__device__ float g_X [TnDn];
__device__ float g_Q [TnDn];
__device__ float g_Kc[TnDn];
__device__ float g_Vc[TnDn];
__device__ float g_part[12 * TnDn];
__device__ float g_xl[Dn];
__device__ float g_tmp[12288];
__device__ float g_ropec[Tn * 32], g_ropes[Tn * 32];
__device__ __nv_bfloat16 g_XNh[TnDn], g_XNl[TnDn];
__device__ __nv_bfloat16 g_Ah [TnDn], g_Al [TnDn];
__device__ __nv_bfloat16 g_Hh [TnFn], g_Hl [TnFn];
__device__ __nv_bfloat16 g_hrh[Fn], g_hrl[Fn];

// ---- helpers ----
__device__ __forceinline__ uint32_t smem_u32(const void* p) {
    uint32_t a;
    asm("{ .reg .u64 t; cvta.to.shared.u64 t, %1; cvt.u32.u64 %0, t; }" : "=r"(a) : "l"(p));
    return a;
}
#define LDSM_X4(r0, r1, r2, r3, a) \
    asm volatile("ldmatrix.sync.aligned.m8n8.x4.shared.b16 {%0,%1,%2,%3}, [%4];" \
                 : "=r"(r0), "=r"(r1), "=r"(r2), "=r"(r3) : "r"(a))

__device__ __forceinline__ void mma_bf16(float* d, const uint32_t* a, const uint32_t* b) {
    asm volatile("mma.sync.aligned.m16n8k16.row.col.f32.bf16.bf16.f32 "
                 "{%0,%1,%2,%3}, {%4,%5,%6,%7}, {%8,%9}, {%0,%1,%2,%3};"
                 : "+f"(d[0]), "+f"(d[1]), "+f"(d[2]), "+f"(d[3])
                 : "r"(a[0]), "r"(a[1]), "r"(a[2]), "r"(a[3]), "r"(b[0]), "r"(b[1]));
}
__device__ __forceinline__ void cp16(uint32_t dst, const void* src) {
    asm volatile("cp.async.cg.shared.global [%0], [%1], 16;" :: "r"(dst), "l"(src));
}
#define CP_COMMIT() asm volatile("cp.async.commit_group;")
#define CP_WAIT0()  asm volatile("cp.async.wait_group 0;")

// ---- GEMM core (r14-proven): C[128x64] = Ahl[128,K]*W[K,n0:n0+64).
// 256 threads (8 warps, one 16-row slab each), double-buffered smem.
#define PITCHB 144
#define SM_AH(s) ((s) * 18432)
#define SM_AL(s) (36864 + (s) * 18432)
#define SM_BH(s) (73728 + (s) * 9216)
#define SM_BL(s) (92160 + (s) * 9216)
#define SMEM_BYTES 110592

__device__ void gemm_core(const __nv_bfloat16* __restrict__ Ah,
                          const __nv_bfloat16* __restrict__ Al, int lda,
                          const float* __restrict__ B, int ldb,
                          float* __restrict__ Cp, int ldc,
                          int k0, int nkb, int n0)
{
    extern __shared__ unsigned char sm[];
    const uint32_t smb = smem_u32(sm);
    const int tid = threadIdx.x, w = tid >> 5, lane = tid & 31;
    const int gID = lane >> 2, tig = lane & 3;

    float c[8][4] = {};

    const int bkk0 = (tid & 15) << 2;   // B: 4-row k subgroup
    const int bn4  = (tid >> 4) << 2;   // B: 4 consecutive n
    const int a_r = lane & 15, a_h = lane >> 4;
    const int b_nr = ((lane >> 4) << 3) | (lane & 7);
    const int b_kh = (lane >> 3) & 1;

    // prologue: A(0) via cp.async (4 chunks/thread), B(0) into regs
    {
#pragma unroll
        for (int j = 0; j < 4; j++) {
            int idx = tid + j * 256;
            int m = idx >> 3, k8 = (idx & 7) << 3;
            uint32_t off = (uint32_t)m * PITCHB + k8 * 2;
            cp16(smb + SM_AH(0) + off, Ah + (size_t)m * lda + k0 + k8);
            cp16(smb + SM_AL(0) + off, Al + (size_t)m * lda + k0 + k8);
        }
        CP_COMMIT();
    }
    float4 f[4];
#pragma unroll
    for (int j = 0; j < 4; j++)
        f[j] = *(const float4*)(B + (size_t)(k0 + bkk0 + j) * ldb + n0 + bn4);

    for (int it = 0; it < nkb; ++it) {
        const int buf = it & 1;
        const int kc = k0 + it * 64;

        // convert current B regs -> smem(buf), hi/lo
#pragma unroll
        for (int i = 0; i < 4; i++) {
            union { __nv_bfloat16 b[4]; uint2 v; } hb, lb;
#pragma unroll
            for (int j = 0; j < 4; j++) {
                float x = (i == 0) ? f[j].x : (i == 1) ? f[j].y : (i == 2) ? f[j].z : f[j].w;
                __nv_bfloat16 hh = __float2bfloat16(x);
                hb.b[j] = hh;
                lb.b[j] = __float2bfloat16(x - __bfloat162float(hh));
            }
            uint32_t off = (uint32_t)(bn4 + i) * PITCHB + bkk0 * 2;
            *(uint2*)(sm + SM_BH(buf) + off) = hb.v;
            *(uint2*)(sm + SM_BL(buf) + off) = lb.v;
        }
        CP_WAIT0();
        __syncthreads();

        // prefetch next iteration before compute
        if (it + 1 < nkb) {
            const int kn = kc + 64;
#pragma unroll
            for (int j = 0; j < 4; j++) {
                int idx = tid + j * 256;
                int m = idx >> 3, k8 = (idx & 7) << 3;
                uint32_t off = (uint32_t)m * PITCHB + k8 * 2;
                cp16(smb + SM_AH(buf ^ 1) + off, Ah + (size_t)m * lda + kn + k8);
                cp16(smb + SM_AL(buf ^ 1) + off, Al + (size_t)m * lda + kn + k8);
            }
            CP_COMMIT();
#pragma unroll
            for (int j = 0; j < 4; j++)
                f[j] = *(const float4*)(B + (size_t)(kn + bkk0 + j) * ldb + n0 + bn4);
        }

        const uint32_t aH = smb + SM_AH(buf), aL = smb + SM_AL(buf);
        const uint32_t bH = smb + SM_BH(buf), bL = smb + SM_BL(buf);
#pragma unroll
        for (int s = 0; s < 4; s++) {
            uint32_t ah[4], al[4], bh[8][2], bl[8][2];
            uint32_t ao = (uint32_t)(w * 16 + a_r) * PITCHB + (s * 16 + a_h * 8) * 2;
            LDSM_X4(ah[0], ah[1], ah[2], ah[3], aH + ao);
            LDSM_X4(al[0], al[1], al[2], al[3], aL + ao);
#pragma unroll
            for (int np = 0; np < 4; np++) {
                uint32_t bo = (uint32_t)(np * 16 + b_nr) * PITCHB
                            + (s * 16 + b_kh * 8) * 2;
                LDSM_X4(bh[np*2][0], bh[np*2][1], bh[np*2+1][0], bh[np*2+1][1], bH + bo);
                LDSM_X4(bl[np*2][0], bl[np*2][1], bl[np*2+1][0], bl[np*2+1][1], bL + bo);
            }
#pragma unroll
            for (int nt = 0; nt < 8; nt++) {
                mma_bf16(c[nt], ah, bh[nt]);
                mma_bf16(c[nt], ah, bl[nt]);
                mma_bf16(c[nt], al, bh[nt]);
            }
        }
    }

#pragma unroll
    for (int nt = 0; nt < 8; nt++) {
        int row = w * 16 + gID;
        int col = n0 + nt * 8 + tig * 2;
        *(float2*)(Cp + (size_t)row * ldc + col) = make_float2(c[nt][0], c[nt][1]);
        *(float2*)(Cp + (size_t)(row + 8) * ldc + col) = make_float2(c[nt][2], c[nt][3]);
    }
}

// ---- GEMM wrappers ----
__global__ void __launch_bounds__(256)
kg_qkv(const float* __restrict__ Wq, const float* __restrict__ Wk,
       const float* __restrict__ Wv) {
    const float* W = (blockIdx.z == 0) ? Wq : (blockIdx.z == 1) ? Wk : Wv;
    float* Cp = g_part + (size_t)(blockIdx.z * 4 + blockIdx.y) * TnDn;
    gemm_core(g_XNh, g_XNl, Dn, W, Dn, Cp, Dn, blockIdx.y * 256, 4, blockIdx.x * 64);
}
__global__ void __launch_bounds__(256)
kg_wo(const float* __restrict__ Wo) {
    float* Cp = g_part + (size_t)blockIdx.y * TnDn;
    gemm_core(g_Ah, g_Al, Dn, Wo, Dn, Cp, Dn, blockIdx.y * 128, 2, blockIdx.x * 64);
}
__global__ void __launch_bounds__(256)
kg_gu(const float* __restrict__ Wg, const float* __restrict__ Wu) {
    const float* W = (blockIdx.z == 0) ? Wg : Wu;
    float* Cp = g_part + (size_t)(blockIdx.z * 2 + blockIdx.y) * TnFn;
    gemm_core(g_XNh, g_XNl, Dn, W, Fn, Cp, Fn, blockIdx.y * 512, 8, blockIdx.x * 64);
}
__global__ void __launch_bounds__(256)
kg_down(const float* __restrict__ Wd) {
    float* Cp = g_part + (size_t)blockIdx.y * TnDn;
    gemm_core(g_Hh, g_Hl, Fn, Wd, Dn, Cp, Dn, blockIdx.y * 256, 4, blockIdx.x * 64);
}

// ---- elementwise / reductions ----
__device__ __forceinline__ float blockReduceSum(float v) {
    __shared__ float red[32];
    __shared__ float tot;
    int lane = threadIdx.x & 31, warp = threadIdx.x >> 5;
#pragma unroll
    for (int o = 16; o > 0; o >>= 1) v += __shfl_xor_sync(0xffffffffu, v, o);
    if (lane == 0) red[warp] = v;
    __syncthreads();
    int nw = (blockDim.x + 31) >> 5;
    if (warp == 0) {
        float x = (threadIdx.x < nw) ? red[threadIdx.x] : 0.f;
#pragma unroll
        for (int o = 16; o > 0; o >>= 1) x += __shfl_xor_sync(0xffffffffu, x, o);
        if (threadIdx.x == 0) tot = x;
    }
    __syncthreads();
    return tot;
}

// RoPE table init (fp64 trig; r15 proved this exact kernel is guard-clean)
__global__ void k_rope_init() {
    int t = blockIdx.x, d = threadIdx.x;
    double inv = pow(10000.0, -(double)d / 32.0);
    double ang = (double)t * inv;
    g_ropec[t * 32 + d] = (float)cos(ang);
    g_ropes[t * 32 + d] = (float)sin(ang);
}

__global__ void k_embed(const int* __restrict__ ids, const float* __restrict__ emb) {
    int t = blockIdx.x;
    int row = ids[t];
    const float4* src = (const float4*)(emb + (size_t)row * Dn);
    float4* dst = (float4*)(g_X + (size_t)t * Dn);
    for (int i = threadIdx.x; i < Dn / 4; i += blockDim.x) dst[i] = src[i];
}

__global__ void k_addnorm(int nparts, const float* __restrict__ w) {
    int t = blockIdx.x;
    int d4 = threadIdx.x * 4;
    float4 acc = *(const float4*)(g_X + (size_t)t * Dn + d4);
    for (int p = 0; p < nparts; p++) {
        float4 pv = *(const float4*)(g_part + (size_t)p * TnDn + (size_t)t * Dn + d4);
        acc.x += pv.x; acc.y += pv.y; acc.z += pv.z; acc.w += pv.w;
    }
    *(float4*)(g_X + (size_t)t * Dn + d4) = acc;
    float ss = acc.x * acc.x + acc.y * acc.y + acc.z * acc.z + acc.w * acc.w;
    ss = blockReduceSum(ss);
    float inv = rsqrtf(ss / (float)Dn + 1e-5f);
    float4 wv = *(const float4*)(w + d4);
    float xn[4] = { acc.x * inv * wv.x, acc.y * inv * wv.y,
                    acc.z * inv * wv.z, acc.w * inv * wv.w };
#pragma unroll
    for (int i = 0; i < 4; i++) {
        __nv_bfloat16 hh = __float2bfloat16(xn[i]);
        g_XNh[(size_t)t * Dn + d4 + i] = hh;
        g_XNl[(size_t)t * Dn + d4 + i] = __float2bfloat16(xn[i] - __bfloat162float(hh));
    }
}

// QKV split-K reduce + RoPE via table. grid=Tn, block=512.
__global__ void k_qkv_rr() {
    int t = blockIdx.x;
    int hh = threadIdx.x >> 5, d = threadIdx.x & 31;
    float c = g_ropec[t * 32 + d], s = g_ropes[t * 32 + d];
    int off = t * Dn + hh * DHn + d;
#pragma unroll
    for (int m = 0; m < 3; m++) {
        size_t base = (size_t)(m * 4) * TnDn + off;
        float s0 = 0.f, s1 = 0.f;
#pragma unroll
        for (int p = 0; p < 4; p++) {
            s0 += g_part[base + (size_t)p * TnDn];
            s1 += g_part[base + (size_t)p * TnDn + 32];
        }
        float o0, o1;
        if (m < 2) { o0 = s0 * c - s1 * s; o1 = s1 * c + s0 * s; }
        else       { o0 = s0; o1 = s1; }
        float* dst = (m == 0) ? g_Q : (m == 1) ? g_Kc : g_Vc;
        dst[off] = o0;
        dst[off + 32] = o1;
    }
}

__global__ void k_silu() {
    int i = blockIdx.x * blockDim.x + threadIdx.x;
    float g = g_part[i] + g_part[(size_t)TnFn + i];
    float u = g_part[2 * (size_t)TnFn + i] + g_part[3 * (size_t)TnFn + i];
    float sv = g / (1.f + expf(-g));
    float r = sv * u;
    __nv_bfloat16 hh = __float2bfloat16(r);
    g_Hh[i] = hh;
    g_Hl[i] = __float2bfloat16(r - __bfloat162float(hh));
}

// ---- attention: 16 queries per block (r14-proven) ----
__global__ void __launch_bounds__(256) k_attn(int qg0) {
    int qg = qg0 + blockIdx.x;
    int hed = blockIdx.y;
    int tid = threadIdx.x, w = tid >> 5, lane = tid & 31;
    __shared__ float KV[Tn][DHn + 1];
    __shared__ float Qs[16][DHn];
    __shared__ float Ps[16][Tn + 1];

    for (int idx = tid; idx < Tn * DHn; idx += 256) {
        int r = idx >> 6, c = idx & 63;
        KV[r][c] = g_Kc[(size_t)r * Dn + hed * DHn + c];
    }
    for (int idx = tid; idx < 16 * DHn; idx += 256) {
        int r = idx >> 6, c = idx & 63;
        Qs[r][c] = g_Q[(size_t)(qg * 16 + r) * Dn + hed * DHn + c];
    }
    __syncthreads();

#pragma unroll
    for (int sub = 0; sub < 2; sub++) {
        int ql = w * 2 + sub;
        int q = qg * 16 + ql;
        float s[4];
#pragma unroll
        for (int jj = 0; jj < 4; jj++) {
            int j = jj * 32 + lane;
            if (j <= q) {
                float acc = 0.f;
#pragma unroll
                for (int d = 0; d < DHn; d++) acc = fmaf(Qs[ql][d], KV[j][d], acc);
                s[jj] = acc * 0.125f;
            } else s[jj] = -1e9f;
        }
        float m = fmaxf(fmaxf(s[0], s[1]), fmaxf(s[2], s[3]));
#pragma unroll
        for (int o = 16; o > 0; o >>= 1) m = fmaxf(m, __shfl_xor_sync(0xffffffffu, m, o));
        float e[4], sum = 0.f;
#pragma unroll
        for (int jj = 0; jj < 4; jj++) { e[jj] = expf(s[jj] - m); sum += e[jj]; }
#pragma unroll
        for (int o = 16; o > 0; o >>= 1) sum += __shfl_xor_sync(0xffffffffu, sum, o);
#pragma unroll
        for (int jj = 0; jj < 4; jj++) Ps[ql][jj * 32 + lane] = e[jj] / sum;
    }
    __syncthreads();

    for (int idx = tid; idx < Tn * DHn; idx += 256) {
        int r = idx >> 6, c = idx & 63;
        KV[r][c] = g_Vc[(size_t)r * Dn + hed * DHn + c];
    }
    __syncthreads();

#pragma unroll
    for (int sub = 0; sub < 2; sub++) {
        int ql = w * 2 + sub;
        int q = qg * 16 + ql;
        float o0 = 0.f, o1 = 0.f;
#pragma unroll 4
        for (int j = 0; j < Tn; j++) {
            float p = Ps[ql][j];
            o0 = fmaf(p, KV[j][lane], o0);
            o1 = fmaf(p, KV[j][lane + 32], o1);
        }
        size_t oi = (size_t)q * Dn + hed * DHn + lane;
        __nv_bfloat16 h0 = __float2bfloat16(o0);
        g_Ah[oi] = h0;
        g_Al[oi] = __float2bfloat16(o0 - __bfloat162float(h0));
        __nv_bfloat16 h1 = __float2bfloat16(o1);
        g_Ah[oi + 32] = h1;
        g_Al[oi + 32] = __float2bfloat16(o1 - __bfloat162float(h1));
    }
}

// ---- last-layer GEMV path (token 127 only; device-resolved globals) ----
__global__ void k_gemv(int src, int outoff, const float* __restrict__ W,
                       int K, int N) {
    __shared__ float red[256];
    const __nv_bfloat16 *xh, *xl;
    if (src == 0)      { xh = g_Ah  + (size_t)(Tn - 1) * Dn; xl = g_Al  + (size_t)(Tn - 1) * Dn; }
    else if (src == 1) { xh = g_XNh + (size_t)(Tn - 1) * Dn; xl = g_XNl + (size_t)(Tn - 1) * Dn; }
    else               { xh = g_hrh;                          xl = g_hrl; }
    int nsub = threadIdx.x & 15, ks = threadIdx.x >> 4;
    int n = blockIdx.x * 16 + nsub;
    float s = 0.f;
    for (int k = ks; k < K; k += 16) {
        float x = __bfloat162float(xh[k]) + __bfloat162float(xl[k]);
        s = fmaf(x, W[(size_t)k * N + n], s);
    }
    red[threadIdx.x] = s;
    __syncthreads();
    if (threadIdx.x < 16) {
        float t = 0.f;
#pragma unroll
        for (int j = 0; j < 16; j++) t += red[threadIdx.x + 16 * j];
        g_tmp[outoff + blockIdx.x * 16 + threadIdx.x] = t;
    }
}

__global__ void k_addnorm_last(const float* __restrict__ w) {
    int d4 = threadIdx.x * 4;
    size_t ro = (size_t)(Tn - 1) * Dn;
    float4 acc = *(const float4*)(g_X + ro + d4);
    float4 pv = *(const float4*)(g_tmp + d4);
    acc.x += pv.x; acc.y += pv.y; acc.z += pv.z; acc.w += pv.w;
    *(float4*)(g_X + ro + d4) = acc;
    float ss = acc.x * acc.x + acc.y * acc.y + acc.z * acc.z + acc.w * acc.w;
    ss = blockReduceSum(ss);
    float inv = rsqrtf(ss / (float)Dn + 1e-5f);
    float4 wv = *(const float4*)(w + d4);
    float xn[4] = { acc.x * inv * wv.x, acc.y * inv * wv.y,
                    acc.z * inv * wv.z, acc.w * inv * wv.w };
#pragma unroll
    for (int i = 0; i < 4; i++) {
        __nv_bfloat16 hh = __float2bfloat16(xn[i]);
        g_XNh[ro + d4 + i] = hh;
        g_XNl[ro + d4 + i] = __float2bfloat16(xn[i] - __bfloat162float(hh));
    }
}

__global__ void k_silu_last() {
    int i = blockIdx.x * blockDim.x + threadIdx.x;
    if (i < Fn) {
        float g = g_tmp[2048 + i], u = g_tmp[5120 + i];
        float sv = g / (1.f + expf(-g));
        float r = sv * u;
        __nv_bfloat16 hh = __float2bfloat16(r);
        g_hrh[i] = hh;
        g_hrl[i] = __float2bfloat16(r - __bfloat162float(hh));
    }
}

__global__ void k_finalnorm_last(const float* __restrict__ w) {
    int d4 = threadIdx.x * 4;
    size_t ro = (size_t)(Tn - 1) * Dn;
    float4 xv = *(const float4*)(g_X + ro + d4);
    float4 dv = *(const float4*)(g_tmp + 8192 + d4);
    xv.x += dv.x; xv.y += dv.y; xv.z += dv.z; xv.w += dv.w;
    float ss = xv.x * xv.x + xv.y * xv.y + xv.z * xv.z + xv.w * xv.w;
    ss = blockReduceSum(ss);
    float inv = rsqrtf(ss / (float)Dn + 1e-5f);
    float4 wv = *(const float4*)(w + d4);
    *(float4*)(g_xl + d4) = make_float4(xv.x * inv * wv.x, xv.y * inv * wv.y,
                                        xv.z * inv * wv.z, xv.w * inv * wv.w);
}

__global__ void k_logits(const float* __restrict__ emb, float* __restrict__ out) {
    __shared__ float4 xs[Dn / 4];
    for (int i = threadIdx.x; i < Dn / 4; i += blockDim.x)
        xs[i] = ((const float4*)g_xl)[i];
    __syncthreads();
    int warp = threadIdx.x >> 5, lane = threadIdx.x & 31;
    int row = blockIdx.x * 8 + warp;
    if (row < Vn) {
        const float4* e4 = (const float4*)(emb + (size_t)row * Dn);
        float s = 0.f;
#pragma unroll
        for (int k = lane; k < Dn / 4; k += 32) {
            float4 a = e4[k], b = xs[k];
            s += a.x * b.x + a.y * b.y + a.z * b.z + a.w * b.w;
        }
#pragma unroll
        for (int o = 16; o > 0; o >>= 1) s += __shfl_xor_sync(0xffffffffu, s, o);
        if (lane == 0) out[row] = s;
    }
}

// ---- host ----
extern "C" void kernel_launch(void* const* d_in, const int* in_sizes, int n_in,
                              void* d_out, int out_size) {
    const int*   ids       = (const int*)  d_in[0];
    const float* emb       = (const float*)d_in[1];
    const float* Wq        = (const float*)d_in[2];
    const float* Wk        = (const float*)d_in[3];
    const float* Wv        = (const float*)d_in[4];
    const float* Wo        = (const float*)d_in[5];
    const float* Wg        = (const float*)d_in[6];
    const float* Wu        = (const float*)d_in[7];
    const float* Wd        = (const float*)d_in[8];
    const float* attn_norm = (const float*)d_in[9];
    const float* ffn_norm  = (const float*)d_in[10];
    const float* norm_out  = (const float*)d_in[11];
    float* out = (float*)d_out;

    cudaFuncSetAttribute(kg_qkv,  cudaFuncAttributeMaxDynamicSharedMemorySize, SMEM_BYTES);
    cudaFuncSetAttribute(kg_wo,   cudaFuncAttributeMaxDynamicSharedMemorySize, SMEM_BYTES);
    cudaFuncSetAttribute(kg_gu,   cudaFuncAttributeMaxDynamicSharedMemorySize, SMEM_BYTES);
    cudaFuncSetAttribute(kg_down, cudaFuncAttributeMaxDynamicSharedMemorySize, SMEM_BYTES);

    k_rope_init<<<Tn, 32>>>();
    k_embed<<<Tn, 256>>>(ids, emb);

    for (int l = 0; l < Ln - 1; l++) {
        const float* wq = Wq + (size_t)l * Dn * Dn;
        const float* wk = Wk + (size_t)l * Dn * Dn;
        const float* wv = Wv + (size_t)l * Dn * Dn;
        const float* wo = Wo + (size_t)l * Dn * Dn;
        const float* wg = Wg + (size_t)l * Dn * Fn;
        const float* wu = Wu + (size_t)l * Dn * Fn;
        const float* wd = Wd + (size_t)l * Fn * Dn;

        k_addnorm<<<Tn, 256>>>(l == 0 ? 0 : 11, attn_norm + (size_t)l * Dn);
        kg_qkv<<<dim3(16, 4, 3), 256, SMEM_BYTES>>>(wq, wk, wv);
        k_qkv_rr<<<Tn, 512>>>();
        k_attn<<<dim3(8, Hn), 256>>>(0);
        kg_wo<<<dim3(16, 8), 256, SMEM_BYTES>>>(wo);
        k_addnorm<<<Tn, 256>>>(8, ffn_norm + (size_t)l * Dn);
        kg_gu<<<dim3(44, 2, 2), 256, SMEM_BYTES>>>(wg, wu);
        k_silu<<<TnFn / 256, 256>>>();
        kg_down<<<dim3(16, 11), 256, SMEM_BYTES>>>(wd);
    }

    // layer 7: K/V for all tokens, everything else token 127 only
    {
        const int l = Ln - 1;
        const float* wq = Wq + (size_t)l * Dn * Dn;
        const float* wk = Wk + (size_t)l * Dn * Dn;
        const float* wv = Wv + (size_t)l * Dn * Dn;
        const float* wo = Wo + (size_t)l * Dn * Dn;
        const float* wg = Wg + (size_t)l * Dn * Fn;
        const float* wu = Wu + (size_t)l * Dn * Fn;
        const float* wd = Wd + (size_t)l * Fn * Dn;

        k_addnorm<<<Tn, 256>>>(11, attn_norm + (size_t)l * Dn);
        kg_qkv<<<dim3(16, 4, 3), 256, SMEM_BYTES>>>(wq, wk, wv);
        k_qkv_rr<<<Tn, 512>>>();
        k_attn<<<dim3(1, Hn), 256>>>(7);
        k_gemv<<<Dn / 16, 256>>>(0, 0,    wo, Dn, Dn);
        k_addnorm_last<<<1, 256>>>(ffn_norm + (size_t)l * Dn);
        k_gemv<<<Fn / 16, 256>>>(1, 2048, wg, Dn, Fn);
        k_gemv<<<Fn / 16, 256>>>(1, 5120, wu, Dn, Fn);
        k_silu_last<<<(Fn + 255) / 256, 256>>>();
        k_gemv<<<Dn / 16, 256>>>(2, 8192, wd, Fn, Dn);
    }

    k_finalnorm_last<<<1, 256>>>(norm_out);
    k_logits<<<(Vn + 7) / 8, 256>>>(emb, out);
}

// round 17
// speedup vs baseline: 1.1973x; 1.1343x over previous
#include <cuda_runtime.h>
#include <cuda_bf16.h>
#include <math.h>
#include <stdint.h>

#define Tn  128
#define Dn  1024
#define Ln  8
#define Hn  16
#define Fn  2816
#define DHn 64
#define Vn  32000
#define TnDn (Tn*Dn)
#define TnFn (Tn*Fn)

// ---- scratch ----
__device__ float g_X [TnDn];
__device__ float g_Q [TnDn];
__device__ float g_Kc[TnDn];
__device__ float g_Vc[TnDn];
__device__ float g_part[12 * TnDn];
__device__ float g_xl[Dn];
__device__ float g_tmp[12288];
__device__ float g_ropec[Tn * 32], g_ropes[Tn * 32];
__device__ __nv_bfloat16 g_XNh[TnDn], g_XNl[TnDn];
__device__ __nv_bfloat16 g_Ah [TnDn], g_Al [TnDn];
__device__ __nv_bfloat16 g_Hh [TnFn], g_Hl [TnFn];
__device__ __nv_bfloat16 g_hrh[Fn], g_hrl[Fn];

// ---- helpers ----
__device__ __forceinline__ uint32_t smem_u32(const void* p) {
    uint32_t a;
    asm("{ .reg .u64 t; cvta.to.shared.u64 t, %1; cvt.u32.u64 %0, t; }" : "=r"(a) : "l"(p));
    return a;
}
#define LDSM_X4(r0, r1, r2, r3, a) \
    asm volatile("ldmatrix.sync.aligned.m8n8.x4.shared.b16 {%0,%1,%2,%3}, [%4];" \
                 : "=r"(r0), "=r"(r1), "=r"(r2), "=r"(r3) : "r"(a))
#define LDSM_X4T(r0, r1, r2, r3, a) \
    asm volatile("ldmatrix.sync.aligned.m8n8.x4.trans.shared.b16 {%0,%1,%2,%3}, [%4];" \
                 : "=r"(r0), "=r"(r1), "=r"(r2), "=r"(r3) : "r"(a))

__device__ __forceinline__ void mma_bf16(float* d, const uint32_t* a, const uint32_t* b) {
    asm volatile("mma.sync.aligned.m16n8k16.row.col.f32.bf16.bf16.f32 "
                 "{%0,%1,%2,%3}, {%4,%5,%6,%7}, {%8,%9}, {%0,%1,%2,%3};"
                 : "+f"(d[0]), "+f"(d[1]), "+f"(d[2]), "+f"(d[3])
                 : "r"(a[0]), "r"(a[1]), "r"(a[2]), "r"(a[3]), "r"(b[0]), "r"(b[1]));
}
__device__ __forceinline__ void cp16(uint32_t dst, const void* src) {
    asm volatile("cp.async.cg.shared.global [%0], [%1], 16;" :: "r"(dst), "l"(src));
}
#define CP_COMMIT() asm volatile("cp.async.commit_group;")
#define CP_WAIT0()  asm volatile("cp.async.wait_group 0;")

// ---- GEMM core: C[128x64] = Ahl[128,K]*W[K,n0:n0+64).
// 256 threads (8 warps, one 16-row slab each), double-buffered smem.
// B staged K-MAJOR [k][n] (coalesced LDG), fragments via ldmatrix.trans.
#define PITCHB 144
#define SM_AH(s) ((s) * 18432)
#define SM_AL(s) (36864 + (s) * 18432)
#define SM_BH(s) (73728 + (s) * 9216)
#define SM_BL(s) (92160 + (s) * 9216)
#define SMEM_BYTES 110592

__device__ void gemm_core(const __nv_bfloat16* __restrict__ Ah,
                          const __nv_bfloat16* __restrict__ Al, int lda,
                          const float* __restrict__ B, int ldb,
                          float* __restrict__ Cp, int ldc,
                          int k0, int nkb, int n0)
{
    extern __shared__ unsigned char sm[];
    const uint32_t smb = smem_u32(sm);
    const int tid = threadIdx.x, w = tid >> 5, lane = tid & 31;
    const int gID = lane >> 2, tig = lane & 3;

    float c[8][4] = {};

    const int b_r  = tid >> 4;          // k row within 16-row group
    const int b_c4 = (tid & 15) << 2;   // n col base (x4) -> coalesced rows
    const int a_r = lane & 15, a_h = lane >> 4;
    const int b_kr = lane & 15;         // trans-ldmatrix k row
    const int b_nh = lane >> 4;         // trans-ldmatrix n half

    // prologue: A(0) via cp.async (4 chunks/thread), B(0) into regs (coalesced)
    {
#pragma unroll
        for (int j = 0; j < 4; j++) {
            int idx = tid + j * 256;
            int m = idx >> 3, k8 = (idx & 7) << 3;
            uint32_t off = (uint32_t)m * PITCHB + k8 * 2;
            cp16(smb + SM_AH(0) + off, Ah + (size_t)m * lda + k0 + k8);
            cp16(smb + SM_AL(0) + off, Al + (size_t)m * lda + k0 + k8);
        }
        CP_COMMIT();
    }
    float4 f[4];
#pragma unroll
    for (int j = 0; j < 4; j++)
        f[j] = *(const float4*)(B + (size_t)(k0 + b_r + 16 * j) * ldb + n0 + b_c4);

    for (int it = 0; it < nkb; ++it) {
        const int buf = it & 1;
        const int kc = k0 + it * 64;

        // convert current B regs -> smem(buf) k-major, hi/lo
#pragma unroll
        for (int j = 0; j < 4; j++) {
            union { __nv_bfloat16 b[4]; uint2 v; } hb, lb;
            float xv0 = f[j].x, xv1 = f[j].y, xv2 = f[j].z, xv3 = f[j].w;
            __nv_bfloat16 h0 = __float2bfloat16(xv0);
            __nv_bfloat16 h1 = __float2bfloat16(xv1);
            __nv_bfloat16 h2 = __float2bfloat16(xv2);
            __nv_bfloat16 h3 = __float2bfloat16(xv3);
            hb.b[0] = h0; hb.b[1] = h1; hb.b[2] = h2; hb.b[3] = h3;
            lb.b[0] = __float2bfloat16(xv0 - __bfloat162float(h0));
            lb.b[1] = __float2bfloat16(xv1 - __bfloat162float(h1));
            lb.b[2] = __float2bfloat16(xv2 - __bfloat162float(h2));
            lb.b[3] = __float2bfloat16(xv3 - __bfloat162float(h3));
            uint32_t off = (uint32_t)(b_r + 16 * j) * PITCHB + b_c4 * 2;
            *(uint2*)(sm + SM_BH(buf) + off) = hb.v;
            *(uint2*)(sm + SM_BL(buf) + off) = lb.v;
        }
        CP_WAIT0();
        __syncthreads();

        // prefetch next iteration before compute
        if (it + 1 < nkb) {
            const int kn = kc + 64;
#pragma unroll
            for (int j = 0; j < 4; j++) {
                int idx = tid + j * 256;
                int m = idx >> 3, k8 = (idx & 7) << 3;
                uint32_t off = (uint32_t)m * PITCHB + k8 * 2;
                cp16(smb + SM_AH(buf ^ 1) + off, Ah + (size_t)m * lda + kn + k8);
                cp16(smb + SM_AL(buf ^ 1) + off, Al + (size_t)m * lda + kn + k8);
            }
            CP_COMMIT();
#pragma unroll
            for (int j = 0; j < 4; j++)
                f[j] = *(const float4*)(B + (size_t)(kn + b_r + 16 * j) * ldb + n0 + b_c4);
        }

        const uint32_t aH = smb + SM_AH(buf), aL = smb + SM_AL(buf);
        const uint32_t bH = smb + SM_BH(buf), bL = smb + SM_BL(buf);
#pragma unroll
        for (int s = 0; s < 4; s++) {
            uint32_t ah[4], al[4], bh[8][2], bl[8][2];
            uint32_t ao = (uint32_t)(w * 16 + a_r) * PITCHB + (s * 16 + a_h * 8) * 2;
            LDSM_X4(ah[0], ah[1], ah[2], ah[3], aH + ao);
            LDSM_X4(al[0], al[1], al[2], al[3], aL + ao);
#pragma unroll
            for (int np = 0; np < 4; np++) {
                uint32_t bo = (uint32_t)(s * 16 + b_kr) * PITCHB
                            + (np * 16 + b_nh * 8) * 2;
                LDSM_X4T(bh[np*2][0], bh[np*2][1], bh[np*2+1][0], bh[np*2+1][1], bH + bo);
                LDSM_X4T(bl[np*2][0], bl[np*2][1], bl[np*2+1][0], bl[np*2+1][1], bL + bo);
            }
#pragma unroll
            for (int nt = 0; nt < 8; nt++) {
                mma_bf16(c[nt], ah, bh[nt]);
                mma_bf16(c[nt], ah, bl[nt]);
                mma_bf16(c[nt], al, bh[nt]);
            }
        }
    }

#pragma unroll
    for (int nt = 0; nt < 8; nt++) {
        int row = w * 16 + gID;
        int col = n0 + nt * 8 + tig * 2;
        *(float2*)(Cp + (size_t)row * ldc + col) = make_float2(c[nt][0], c[nt][1]);
        *(float2*)(Cp + (size_t)(row + 8) * ldc + col) = make_float2(c[nt][2], c[nt][3]);
    }
}

// ---- GEMM wrappers ----
__global__ void __launch_bounds__(256)
kg_qkv(const float* __restrict__ Wq, const float* __restrict__ Wk,
       const float* __restrict__ Wv) {
    const float* W = (blockIdx.z == 0) ? Wq : (blockIdx.z == 1) ? Wk : Wv;
    float* Cp = g_part + (size_t)(blockIdx.z * 4 + blockIdx.y) * TnDn;
    gemm_core(g_XNh, g_XNl, Dn, W, Dn, Cp, Dn, blockIdx.y * 256, 4, blockIdx.x * 64);
}
__global__ void __launch_bounds__(256)
kg_wo(const float* __restrict__ Wo) {
    float* Cp = g_part + (size_t)blockIdx.y * TnDn;
    gemm_core(g_Ah, g_Al, Dn, Wo, Dn, Cp, Dn, blockIdx.y * 128, 2, blockIdx.x * 64);
}
__global__ void __launch_bounds__(256)
kg_gu(const float* __restrict__ Wg, const float* __restrict__ Wu) {
    const float* W = (blockIdx.z == 0) ? Wg : Wu;
    float* Cp = g_part + (size_t)(blockIdx.z * 2 + blockIdx.y) * TnFn;
    gemm_core(g_XNh, g_XNl, Dn, W, Fn, Cp, Fn, blockIdx.y * 512, 8, blockIdx.x * 64);
}
__global__ void __launch_bounds__(256)
kg_down(const float* __restrict__ Wd) {
    float* Cp = g_part + (size_t)blockIdx.y * TnDn;
    gemm_core(g_Hh, g_Hl, Fn, Wd, Dn, Cp, Dn, blockIdx.y * 256, 4, blockIdx.x * 64);
}

// ---- elementwise / reductions ----
__device__ __forceinline__ float blockReduceSum(float v) {
    __shared__ float red[32];
    __shared__ float tot;
    int lane = threadIdx.x & 31, warp = threadIdx.x >> 5;
#pragma unroll
    for (int o = 16; o > 0; o >>= 1) v += __shfl_xor_sync(0xffffffffu, v, o);
    if (lane == 0) red[warp] = v;
    __syncthreads();
    int nw = (blockDim.x + 31) >> 5;
    if (warp == 0) {
        float x = (threadIdx.x < nw) ? red[threadIdx.x] : 0.f;
#pragma unroll
        for (int o = 16; o > 0; o >>= 1) x += __shfl_xor_sync(0xffffffffu, x, o);
        if (threadIdx.x == 0) tot = x;
    }
    __syncthreads();
    return tot;
}

__global__ void k_rope_init() {
    int t = blockIdx.x, d = threadIdx.x;
    double inv = pow(10000.0, -(double)d / 32.0);
    double ang = (double)t * inv;
    g_ropec[t * 32 + d] = (float)cos(ang);
    g_ropes[t * 32 + d] = (float)sin(ang);
}

__global__ void k_embed(const int* __restrict__ ids, const float* __restrict__ emb) {
    int t = blockIdx.x;
    int row = ids[t];
    const float4* src = (const float4*)(emb + (size_t)row * Dn);
    float4* dst = (float4*)(g_X + (size_t)t * Dn);
    for (int i = threadIdx.x; i < Dn / 4; i += blockDim.x) dst[i] = src[i];
}

__global__ void k_addnorm(int nparts, const float* __restrict__ w) {
    int t = blockIdx.x;
    int d4 = threadIdx.x * 4;
    float4 acc = *(const float4*)(g_X + (size_t)t * Dn + d4);
    for (int p = 0; p < nparts; p++) {
        float4 pv = *(const float4*)(g_part + (size_t)p * TnDn + (size_t)t * Dn + d4);
        acc.x += pv.x; acc.y += pv.y; acc.z += pv.z; acc.w += pv.w;
    }
    *(float4*)(g_X + (size_t)t * Dn + d4) = acc;
    float ss = acc.x * acc.x + acc.y * acc.y + acc.z * acc.z + acc.w * acc.w;
    ss = blockReduceSum(ss);
    float inv = rsqrtf(ss / (float)Dn + 1e-5f);
    float4 wv = *(const float4*)(w + d4);
    float xn[4] = { acc.x * inv * wv.x, acc.y * inv * wv.y,
                    acc.z * inv * wv.z, acc.w * inv * wv.w };
#pragma unroll
    for (int i = 0; i < 4; i++) {
        __nv_bfloat16 hh = __float2bfloat16(xn[i]);
        g_XNh[(size_t)t * Dn + d4 + i] = hh;
        g_XNl[(size_t)t * Dn + d4 + i] = __float2bfloat16(xn[i] - __bfloat162float(hh));
    }
}

__global__ void k_qkv_rr() {
    int t = blockIdx.x;
    int hh = threadIdx.x >> 5, d = threadIdx.x & 31;
    float c = g_ropec[t * 32 + d], s = g_ropes[t * 32 + d];
    int off = t * Dn + hh * DHn + d;
#pragma unroll
    for (int m = 0; m < 3; m++) {
        size_t base = (size_t)(m * 4) * TnDn + off;
        float s0 = 0.f, s1 = 0.f;
#pragma unroll
        for (int p = 0; p < 4; p++) {
            s0 += g_part[base + (size_t)p * TnDn];
            s1 += g_part[base + (size_t)p * TnDn + 32];
        }
        float o0, o1;
        if (m < 2) { o0 = s0 * c - s1 * s; o1 = s1 * c + s0 * s; }
        else       { o0 = s0; o1 = s1; }
        float* dst = (m == 0) ? g_Q : (m == 1) ? g_Kc : g_Vc;
        dst[off] = o0;
        dst[off + 32] = o1;
    }
}

__global__ void k_silu() {
    int i = blockIdx.x * blockDim.x + threadIdx.x;
    float g = g_part[i] + g_part[(size_t)TnFn + i];
    float u = g_part[2 * (size_t)TnFn + i] + g_part[3 * (size_t)TnFn + i];
    float sv = g / (1.f + expf(-g));
    float r = sv * u;
    __nv_bfloat16 hh = __float2bfloat16(r);
    g_Hh[i] = hh;
    g_Hl[i] = __float2bfloat16(r - __bfloat162float(hh));
}

// ---- attention: 16 queries per block (r14-proven) ----
__global__ void __launch_bounds__(256) k_attn(int qg0) {
    int qg = qg0 + blockIdx.x;
    int hed = blockIdx.y;
    int tid = threadIdx.x, w = tid >> 5, lane = tid & 31;
    __shared__ float KV[Tn][DHn + 1];
    __shared__ float Qs[16][DHn];
    __shared__ float Ps[16][Tn + 1];

    for (int idx = tid; idx < Tn * DHn; idx += 256) {
        int r = idx >> 6, c = idx & 63;
        KV[r][c] = g_Kc[(size_t)r * Dn + hed * DHn + c];
    }
    for (int idx = tid; idx < 16 * DHn; idx += 256) {
        int r = idx >> 6, c = idx & 63;
        Qs[r][c] = g_Q[(size_t)(qg * 16 + r) * Dn + hed * DHn + c];
    }
    __syncthreads();

#pragma unroll
    for (int sub = 0; sub < 2; sub++) {
        int ql = w * 2 + sub;
        int q = qg * 16 + ql;
        float s[4];
#pragma unroll
        for (int jj = 0; jj < 4; jj++) {
            int j = jj * 32 + lane;
            if (j <= q) {
                float acc = 0.f;
#pragma unroll
                for (int d = 0; d < DHn; d++) acc = fmaf(Qs[ql][d], KV[j][d], acc);
                s[jj] = acc * 0.125f;
            } else s[jj] = -1e9f;
        }
        float m = fmaxf(fmaxf(s[0], s[1]), fmaxf(s[2], s[3]));
#pragma unroll
        for (int o = 16; o > 0; o >>= 1) m = fmaxf(m, __shfl_xor_sync(0xffffffffu, m, o));
        float e[4], sum = 0.f;
#pragma unroll
        for (int jj = 0; jj < 4; jj++) { e[jj] = expf(s[jj] - m); sum += e[jj]; }
#pragma unroll
        for (int o = 16; o > 0; o >>= 1) sum += __shfl_xor_sync(0xffffffffu, sum, o);
#pragma unroll
        for (int jj = 0; jj < 4; jj++) Ps[ql][jj * 32 + lane] = e[jj] / sum;
    }
    __syncthreads();

    for (int idx = tid; idx < Tn * DHn; idx += 256) {
        int r = idx >> 6, c = idx & 63;
        KV[r][c] = g_Vc[(size_t)r * Dn + hed * DHn + c];
    }
    __syncthreads();

#pragma unroll
    for (int sub = 0; sub < 2; sub++) {
        int ql = w * 2 + sub;
        int q = qg * 16 + ql;
        float o0 = 0.f, o1 = 0.f;
#pragma unroll 4
        for (int j = 0; j < Tn; j++) {
            float p = Ps[ql][j];
            o0 = fmaf(p, KV[j][lane], o0);
            o1 = fmaf(p, KV[j][lane + 32], o1);
        }
        size_t oi = (size_t)q * Dn + hed * DHn + lane;
        __nv_bfloat16 h0 = __float2bfloat16(o0);
        g_Ah[oi] = h0;
        g_Al[oi] = __float2bfloat16(o0 - __bfloat162float(h0));
        __nv_bfloat16 h1 = __float2bfloat16(o1);
        g_Ah[oi + 32] = h1;
        g_Al[oi + 32] = __float2bfloat16(o1 - __bfloat162float(h1));
    }
}

// ---- last-layer GEMV path (token 127 only; device-resolved globals) ----
__global__ void k_gemv(int src, int outoff, const float* __restrict__ W,
                       int K, int N) {
    __shared__ float red[256];
    const __nv_bfloat16 *xh, *xl;
    if (src == 0)      { xh = g_Ah  + (size_t)(Tn - 1) * Dn; xl = g_Al  + (size_t)(Tn - 1) * Dn; }
    else if (src == 1) { xh = g_XNh + (size_t)(Tn - 1) * Dn; xl = g_XNl + (size_t)(Tn - 1) * Dn; }
    else               { xh = g_hrh;                          xl = g_hrl; }
    int nsub = threadIdx.x & 15, ks = threadIdx.x >> 4;
    int n = blockIdx.x * 16 + nsub;
    float s = 0.f;
    for (int k = ks; k < K; k += 16) {
        float x = __bfloat162float(xh[k]) + __bfloat162float(xl[k]);
        s = fmaf(x, W[(size_t)k * N + n], s);
    }
    red[threadIdx.x] = s;
    __syncthreads();
    if (threadIdx.x < 16) {
        float t = 0.f;
#pragma unroll
        for (int j = 0; j < 16; j++) t += red[threadIdx.x + 16 * j];
        g_tmp[outoff + blockIdx.x * 16 + threadIdx.x] = t;
    }
}

__global__ void k_addnorm_last(const float* __restrict__ w) {
    int d4 = threadIdx.x * 4;
    size_t ro = (size_t)(Tn - 1) * Dn;
    float4 acc = *(const float4*)(g_X + ro + d4);
    float4 pv = *(const float4*)(g_tmp + d4);
    acc.x += pv.x; acc.y += pv.y; acc.z += pv.z; acc.w += pv.w;
    *(float4*)(g_X + ro + d4) = acc;
    float ss = acc.x * acc.x + acc.y * acc.y + acc.z * acc.z + acc.w * acc.w;
    ss = blockReduceSum(ss);
    float inv = rsqrtf(ss / (float)Dn + 1e-5f);
    float4 wv = *(const float4*)(w + d4);
    float xn[4] = { acc.x * inv * wv.x, acc.y * inv * wv.y,
                    acc.z * inv * wv.z, acc.w * inv * wv.w };
#pragma unroll
    for (int i = 0; i < 4; i++) {
        __nv_bfloat16 hh = __float2bfloat16(xn[i]);
        g_XNh[ro + d4 + i] = hh;
        g_XNl[ro + d4 + i] = __float2bfloat16(xn[i] - __bfloat162float(hh));
    }
}

__global__ void k_silu_last() {
    int i = blockIdx.x * blockDim.x + threadIdx.x;
    if (i < Fn) {
        float g = g_tmp[2048 + i], u = g_tmp[5120 + i];
        float sv = g / (1.f + expf(-g));
        float r = sv * u;
        __nv_bfloat16 hh = __float2bfloat16(r);
        g_hrh[i] = hh;
        g_hrl[i] = __float2bfloat16(r - __bfloat162float(hh));
    }
}

__global__ void k_finalnorm_last(const float* __restrict__ w) {
    int d4 = threadIdx.x * 4;
    size_t ro = (size_t)(Tn - 1) * Dn;
    float4 xv = *(const float4*)(g_X + ro + d4);
    float4 dv = *(const float4*)(g_tmp + 8192 + d4);
    xv.x += dv.x; xv.y += dv.y; xv.z += dv.z; xv.w += dv.w;
    float ss = xv.x * xv.x + xv.y * xv.y + xv.z * xv.z + xv.w * xv.w;
    ss = blockReduceSum(ss);
    float inv = rsqrtf(ss / (float)Dn + 1e-5f);
    float4 wv = *(const float4*)(w + d4);
    *(float4*)(g_xl + d4) = make_float4(xv.x * inv * wv.x, xv.y * inv * wv.y,
                                        xv.z * inv * wv.z, xv.w * inv * wv.w);
}

__global__ void k_logits(const float* __restrict__ emb, float* __restrict__ out) {
    __shared__ float4 xs[Dn / 4];
    for (int i = threadIdx.x; i < Dn / 4; i += blockDim.x)
        xs[i] = ((const float4*)g_xl)[i];
    __syncthreads();
    int warp = threadIdx.x >> 5, lane = threadIdx.x & 31;
    int row = blockIdx.x * 8 + warp;
    if (row < Vn) {
        const float4* e4 = (const float4*)(emb + (size_t)row * Dn);
        float s = 0.f;
#pragma unroll
        for (int k = lane; k < Dn / 4; k += 32) {
            float4 a = e4[k], b = xs[k];
            s += a.x * b.x + a.y * b.y + a.z * b.z + a.w * b.w;
        }
#pragma unroll
        for (int o = 16; o > 0; o >>= 1) s += __shfl_xor_sync(0xffffffffu, s, o);
        if (lane == 0) out[row] = s;
    }
}

// ---- host ----
extern "C" void kernel_launch(void* const* d_in, const int* in_sizes, int n_in,
                              void* d_out, int out_size) {
    const int*   ids       = (const int*)  d_in[0];
    const float* emb       = (const float*)d_in[1];
    const float* Wq        = (const float*)d_in[2];
    const float* Wk        = (const float*)d_in[3];
    const float* Wv        = (const float*)d_in[4];
    const float* Wo        = (const float*)d_in[5];
    const float* Wg        = (const float*)d_in[6];
    const float* Wu        = (const float*)d_in[7];
    const float* Wd        = (const float*)d_in[8];
    const float* attn_norm = (const float*)d_in[9];
    const float* ffn_norm  = (const float*)d_in[10];
    const float* norm_out  = (const float*)d_in[11];
    float* out = (float*)d_out;

    cudaFuncSetAttribute(kg_qkv,  cudaFuncAttributeMaxDynamicSharedMemorySize, SMEM_BYTES);
    cudaFuncSetAttribute(kg_wo,   cudaFuncAttributeMaxDynamicSharedMemorySize, SMEM_BYTES);
    cudaFuncSetAttribute(kg_gu,   cudaFuncAttributeMaxDynamicSharedMemorySize, SMEM_BYTES);
    cudaFuncSetAttribute(kg_down, cudaFuncAttributeMaxDynamicSharedMemorySize, SMEM_BYTES);

    k_rope_init<<<Tn, 32>>>();
    k_embed<<<Tn, 256>>>(ids, emb);

    for (int l = 0; l < Ln - 1; l++) {
        const float* wq = Wq + (size_t)l * Dn * Dn;
        const float* wk = Wk + (size_t)l * Dn * Dn;
        const float* wv = Wv + (size_t)l * Dn * Dn;
        const float* wo = Wo + (size_t)l * Dn * Dn;
        const float* wg = Wg + (size_t)l * Dn * Fn;
        const float* wu = Wu + (size_t)l * Dn * Fn;
        const float* wd = Wd + (size_t)l * Fn * Dn;

        k_addnorm<<<Tn, 256>>>(l == 0 ? 0 : 11, attn_norm + (size_t)l * Dn);
        kg_qkv<<<dim3(16, 4, 3), 256, SMEM_BYTES>>>(wq, wk, wv);
        k_qkv_rr<<<Tn, 512>>>();
        k_attn<<<dim3(8, Hn), 256>>>(0);
        kg_wo<<<dim3(16, 8), 256, SMEM_BYTES>>>(wo);
        k_addnorm<<<Tn, 256>>>(8, ffn_norm + (size_t)l * Dn);
        kg_gu<<<dim3(44, 2, 2), 256, SMEM_BYTES>>>(wg, wu);
        k_silu<<<TnFn / 256, 256>>>();
        kg_down<<<dim3(16, 11), 256, SMEM_BYTES>>>(wd);
    }

    // layer 7: K/V for all tokens, everything else token 127 only
    {
        const int l = Ln - 1;
        const float* wq = Wq + (size_t)l * Dn * Dn;
        const float* wk = Wk + (size_t)l * Dn * Dn;
        const float* wv = Wv + (size_t)l * Dn * Dn;
        const float* wo = Wo + (size_t)l * Dn * Dn;
        const float* wg = Wg + (size_t)l * Dn * Fn;
        const float* wu = Wu + (size_t)l * Dn * Fn;
        const float* wd = Wd + (size_t)l * Fn * Dn;

        k_addnorm<<<Tn, 256>>>(11, attn_norm + (size_t)l * Dn);
        kg_qkv<<<dim3(16, 4, 3), 256, SMEM_BYTES>>>(wq, wk, wv);
        k_qkv_rr<<<Tn, 512>>>();
        k_attn<<<dim3(1, Hn), 256>>>(7);
        k_gemv<<<Dn / 16, 256>>>(0, 0,    wo, Dn, Dn);
        k_addnorm_last<<<1, 256>>>(ffn_norm + (size_t)l * Dn);
        k_gemv<<<Fn / 16, 256>>>(1, 2048, wg, Dn, Fn);
        k_gemv<<<Fn / 16, 256>>>(1, 5120, wu, Dn, Fn);
        k_silu_last<<<(Fn + 255) / 256, 256>>>();
        k_gemv<<<Dn / 16, 256>>>(2, 8192, wd, Fn, Dn);
    }

    k_finalnorm_last<<<1, 256>>>(norm_out);
    k_logits<<<(Vn + 7) / 8, 256>>>(emb, out);
}